// round 1
// baseline (speedup 1.0000x reference)
#include <cuda_runtime.h>
#include <math.h>

#define TOKENS     8192
#define MODEL_DIM  4096
#define PROMPT_DIM 64
#define KTOT       (MODEL_DIM + PROMPT_DIM)   // 4160
#define NE         8
#define TPW        7                          // tokens per warp
#define WARPS      8
#define TPB        (TPW * WARPS)              // 56 tokens per block
#define THREADS    256
#define WSTRIDE    4164                       // 4160 + 4 pad: conflict-free stage + read
#define SMEM_BYTES (NE * WSTRIDE * 4)         // 133,248 B

__global__ __launch_bounds__(THREADS, 1)
void topkgate_kernel(const float* __restrict__ x,
                     const float* __restrict__ prompt,
                     const float* __restrict__ W,
                     const float* __restrict__ b,
                     float* __restrict__ out)
{
    extern __shared__ float ws[];   // ws[e * WSTRIDE + d] = W[d][e]

    const int tid = threadIdx.x;

    // ---- Stage W transposed into SMEM (coalesced gmem read; conflict-free STS) ----
    for (int i = tid; i < KTOT * NE; i += THREADS) {
        int d = i >> 3;
        int e = i & 7;
        ws[e * WSTRIDE + d] = W[i];
    }
    __syncthreads();

    const int w    = tid >> 5;
    const int lane = tid & 31;
    const int tbase = blockIdx.x * TPB + w * TPW;

    // Per-token x row pointers (clamped for tail blocks; invalid tokens never written)
    const float* xr[TPW];
#pragma unroll
    for (int m = 0; m < TPW; m++) {
        int t = tbase + m;
        if (t > TOKENS - 1) t = TOKENS - 1;
        xr[m] = x + (size_t)t * MODEL_DIM + 4 * lane;
    }

    float acc[TPW][NE];
#pragma unroll
    for (int m = 0; m < TPW; m++)
#pragma unroll
        for (int e = 0; e < NE; e++) acc[m][e] = 0.0f;

    // ---- Main K loop over MODEL_DIM, 128 floats per chunk, x double-buffered ----
    float4 xc[TPW], xn[TPW];
#pragma unroll
    for (int m = 0; m < TPW; m++) xc[m] = *(const float4*)(xr[m]);

    const int NIT = MODEL_DIM / 128;   // 32
    for (int it = 0; it < NIT; ++it) {
        const int k0 = it * 128;
        if (it + 1 < NIT) {
#pragma unroll
            for (int m = 0; m < TPW; m++)
                xn[m] = *(const float4*)(xr[m] + k0 + 128);
        }

        float4 wv[NE];
        const int wsoff = k0 + 4 * lane;
#pragma unroll
        for (int e = 0; e < NE; e++)
            wv[e] = *(const float4*)&ws[e * WSTRIDE + wsoff];

#pragma unroll
        for (int m = 0; m < TPW; m++) {
            const float4 xv = xc[m];
#pragma unroll
            for (int e = 0; e < NE; e++) {
                acc[m][e] += xv.x * wv[e].x;
                acc[m][e] += xv.y * wv[e].y;
                acc[m][e] += xv.z * wv[e].z;
                acc[m][e] += xv.w * wv[e].w;
            }
        }
#pragma unroll
        for (int m = 0; m < TPW; m++) xc[m] = xn[m];
    }

    // ---- Prompt tail: 64 dims, lanes 0..15 each take 4 dims ----
    if (lane < 16) {
        const int po = 4 * lane;
        float4 wp[NE];
#pragma unroll
        for (int e = 0; e < NE; e++)
            wp[e] = *(const float4*)&ws[e * WSTRIDE + MODEL_DIM + po];
#pragma unroll
        for (int m = 0; m < TPW; m++) {
            int t = tbase + m;
            if (t > TOKENS - 1) t = TOKENS - 1;
            const float4 pv = *(const float4*)(prompt + (size_t)t * PROMPT_DIM + po);
#pragma unroll
            for (int e = 0; e < NE; e++) {
                acc[m][e] += pv.x * wp[e].x;
                acc[m][e] += pv.y * wp[e].y;
                acc[m][e] += pv.z * wp[e].z;
                acc[m][e] += pv.w * wp[e].w;
            }
        }
    }

    // ---- Warp butterfly reduction over lanes (every lane ends with full sums) ----
#pragma unroll
    for (int off = 16; off > 0; off >>= 1) {
#pragma unroll
        for (int m = 0; m < TPW; m++)
#pragma unroll
            for (int e = 0; e < NE; e++)
                acc[m][e] += __shfl_xor_sync(0xffffffffu, acc[m][e], off);
    }

    // ---- Epilogue: lane m handles token (tbase + m) ----
    if (lane < TPW) {
        const int t = tbase + lane;
        if (t < TOKENS) {
            // Static-indexed select of this lane's token accumulators (no local-mem)
            float lg[NE];
#pragma unroll
            for (int m = 0; m < TPW; m++) {
                if (lane == m) {
#pragma unroll
                    for (int e = 0; e < NE; e++) lg[e] = acc[m][e];
                }
            }
#pragma unroll
            for (int e = 0; e < NE; e++) lg[e] += b[e];

            // Top-2, first-index tie-break (matches jax.lax.top_k)
            int i0 = 0; float m0 = lg[0];
#pragma unroll
            for (int e = 1; e < NE; e++)
                if (lg[e] > m0) { m0 = lg[e]; i0 = e; }
            int i1 = -1; float m1 = -INFINITY;
#pragma unroll
            for (int e = 0; e < NE; e++)
                if (e != i0 && lg[e] > m1) { m1 = lg[e]; i1 = e; }

            // Softmax over 8 (max-subtracted), gather top-2, renormalize with EPS clamp
            float s = 0.0f;
#pragma unroll
            for (int e = 0; e < NE; e++) s += __expf(lg[e] - m0);
            const float g0 = 1.0f / s;              // exp(0)/s
            const float g1 = __expf(m1 - m0) / s;
            const float denom = fmaxf(g0 + g1, 1.1920929e-07f);
            const float r0 = g0 / denom;
            const float r1 = g1 / denom;

            // masks: [T, 2, 8] at offset 0 — zero 16 floats, then set the two ones
            float* mrow = out + (size_t)t * 16;
            const float4 z = make_float4(0.f, 0.f, 0.f, 0.f);
            *(float4*)(mrow + 0)  = z;
            *(float4*)(mrow + 4)  = z;
            *(float4*)(mrow + 8)  = z;
            *(float4*)(mrow + 12) = z;
            mrow[i0]     = 1.0f;
            mrow[8 + i1] = 1.0f;

            // gates_s: [T, 2] at offset T*16
            float* grow = out + (size_t)TOKENS * 16 + (size_t)t * 2;
            grow[0] = r0;
            grow[1] = r1;
        }
    }
}

extern "C" void kernel_launch(void* const* d_in, const int* in_sizes, int n_in,
                              void* d_out, int out_size)
{
    const float* x      = (const float*)d_in[0];
    const float* prompt = (const float*)d_in[1];
    const float* W      = (const float*)d_in[2];
    const float* b      = (const float*)d_in[3];
    float* out          = (float*)d_out;

    cudaFuncSetAttribute(topkgate_kernel,
                         cudaFuncAttributeMaxDynamicSharedMemorySize, SMEM_BYTES);

    dim3 grid((TOKENS + TPB - 1) / TPB);   // 147 blocks
    topkgate_kernel<<<grid, THREADS, SMEM_BYTES>>>(x, prompt, W, b, out);
}

// round 2
// speedup vs baseline: 1.4600x; 1.4600x over previous
#include <cuda_runtime.h>
#include <math.h>

#define TOKENS     8192
#define MODEL_DIM  4096
#define PROMPT_DIM 64
#define KTOT       (MODEL_DIM + PROMPT_DIM)   // 4160
#define NE         8
#define TPW        4                          // tokens per warp
#define WARPS      16
#define TPB        (TPW * WARPS)              // 64 tokens per block
#define THREADS    512
#define WSTRIDE    4164                       // 4160 + 4 pad: conflict-free stage + read
#define SMEM_BYTES (NE * WSTRIDE * 4)         // 133,248 B

__global__ __launch_bounds__(THREADS, 1)
void topkgate_kernel(const float* __restrict__ x,
                     const float* __restrict__ prompt,
                     const float* __restrict__ W,
                     const float* __restrict__ b,
                     float* __restrict__ out)
{
    extern __shared__ float ws[];   // ws[e * WSTRIDE + d] = W[d][e]

    const int tid = threadIdx.x;

    // ---- Stage W transposed into SMEM (coalesced gmem read; conflict-free STS) ----
    for (int i = tid; i < KTOT * NE; i += THREADS) {
        int d = i >> 3;
        int e = i & 7;
        ws[e * WSTRIDE + d] = W[i];
    }
    __syncthreads();

    const int w    = tid >> 5;
    const int lane = tid & 31;
    const int tbase = blockIdx.x * TPB + w * TPW;   // grid covers TOKENS exactly

    const float* xr[TPW];
#pragma unroll
    for (int m = 0; m < TPW; m++)
        xr[m] = x + (size_t)(tbase + m) * MODEL_DIM + 4 * lane;

    float acc[TPW][NE];
#pragma unroll
    for (int m = 0; m < TPW; m++)
#pragma unroll
        for (int e = 0; e < NE; e++) acc[m][e] = 0.0f;

    // ---- Main K loop over MODEL_DIM, 128 floats per chunk, x double-buffered ----
    float4 xc[TPW], xn[TPW];
#pragma unroll
    for (int m = 0; m < TPW; m++)
        xc[m] = __ldcs((const float4*)(xr[m]));        // streaming: no reuse

    const int NIT = MODEL_DIM / 128;   // 32
    for (int it = 0; it < NIT; ++it) {
        const int k0 = it * 128;
        if (it + 1 < NIT) {
#pragma unroll
            for (int m = 0; m < TPW; m++)
                xn[m] = __ldcs((const float4*)(xr[m] + k0 + 128));
        }

        float4 wv[NE];
        const int wsoff = k0 + 4 * lane;
#pragma unroll
        for (int e = 0; e < NE; e++)
            wv[e] = *(const float4*)&ws[e * WSTRIDE + wsoff];

#pragma unroll
        for (int m = 0; m < TPW; m++) {
            const float4 xv = xc[m];
#pragma unroll
            for (int e = 0; e < NE; e++) {
                acc[m][e] += xv.x * wv[e].x;
                acc[m][e] += xv.y * wv[e].y;
                acc[m][e] += xv.z * wv[e].z;
                acc[m][e] += xv.w * wv[e].w;
            }
        }
#pragma unroll
        for (int m = 0; m < TPW; m++) xc[m] = xn[m];
    }

    // ---- Prompt tail: 64 dims, lanes 0..15 each take 4 dims ----
    if (lane < 16) {
        const int po = 4 * lane;
        float4 wp[NE];
#pragma unroll
        for (int e = 0; e < NE; e++)
            wp[e] = *(const float4*)&ws[e * WSTRIDE + MODEL_DIM + po];
#pragma unroll
        for (int m = 0; m < TPW; m++) {
            const float4 pv = *(const float4*)(prompt + (size_t)(tbase + m) * PROMPT_DIM + po);
#pragma unroll
            for (int e = 0; e < NE; e++) {
                acc[m][e] += pv.x * wp[e].x;
                acc[m][e] += pv.y * wp[e].y;
                acc[m][e] += pv.z * wp[e].z;
                acc[m][e] += pv.w * wp[e].w;
            }
        }
    }

    // ---- Warp butterfly reduction over lanes (every lane ends with full sums) ----
#pragma unroll
    for (int off = 16; off > 0; off >>= 1) {
#pragma unroll
        for (int m = 0; m < TPW; m++)
#pragma unroll
            for (int e = 0; e < NE; e++)
                acc[m][e] += __shfl_xor_sync(0xffffffffu, acc[m][e], off);
    }

    // ---- Epilogue: lane m handles token (tbase + m) ----
    if (lane < TPW) {
        const int t = tbase + lane;

        // Static-indexed select of this lane's token accumulators (no local-mem)
        float lg[NE];
#pragma unroll
        for (int m = 0; m < TPW; m++) {
            if (lane == m) {
#pragma unroll
                for (int e = 0; e < NE; e++) lg[e] = acc[m][e];
            }
        }
#pragma unroll
        for (int e = 0; e < NE; e++) lg[e] += b[e];

        // Top-2, first-index tie-break (matches jax.lax.top_k)
        int i0 = 0; float m0 = lg[0];
#pragma unroll
        for (int e = 1; e < NE; e++)
            if (lg[e] > m0) { m0 = lg[e]; i0 = e; }
        int i1 = -1; float m1 = -INFINITY;
#pragma unroll
        for (int e = 0; e < NE; e++)
            if (e != i0 && lg[e] > m1) { m1 = lg[e]; i1 = e; }

        // Softmax over 8 (max-subtracted), gather top-2, renormalize with EPS clamp
        float s = 0.0f;
#pragma unroll
        for (int e = 0; e < NE; e++) s += __expf(lg[e] - m0);
        const float g0 = 1.0f / s;              // exp(0)/s
        const float g1 = __expf(m1 - m0) / s;
        const float denom = fmaxf(g0 + g1, 1.1920929e-07f);
        const float r0 = g0 / denom;
        const float r1 = g1 / denom;

        // masks: [T, 2, 8] at offset 0 — zero 16 floats, then set the two ones
        float* mrow = out + (size_t)t * 16;
        const float4 z = make_float4(0.f, 0.f, 0.f, 0.f);
        *(float4*)(mrow + 0)  = z;
        *(float4*)(mrow + 4)  = z;
        *(float4*)(mrow + 8)  = z;
        *(float4*)(mrow + 12) = z;
        mrow[i0]     = 1.0f;
        mrow[8 + i1] = 1.0f;

        // gates_s: [T, 2] at offset T*16
        float* grow = out + (size_t)TOKENS * 16 + (size_t)t * 2;
        grow[0] = r0;
        grow[1] = r1;
    }
}

extern "C" void kernel_launch(void* const* d_in, const int* in_sizes, int n_in,
                              void* d_out, int out_size)
{
    const float* x      = (const float*)d_in[0];
    const float* prompt = (const float*)d_in[1];
    const float* W      = (const float*)d_in[2];
    const float* b      = (const float*)d_in[3];
    float* out          = (float*)d_out;

    cudaFuncSetAttribute(topkgate_kernel,
                         cudaFuncAttributeMaxDynamicSharedMemorySize, SMEM_BYTES);

    dim3 grid(TOKENS / TPB);   // 128 blocks, one wave
    topkgate_kernel<<<grid, THREADS, SMEM_BYTES>>>(x, prompt, W, b, out);
}